// round 8
// baseline (speedup 1.0000x reference)
#include <cuda_runtime.h>

#define TAILB 12.0f
#define MIN_BW 1e-6f
#define MIN_BH 1e-6f
#define MIN_DD 1e-6f

// W2 of the CURRENT layer lives in the constant bank (exactly 64 KB).
// Stored as ulonglong2 so the GEMM reads it with LDC.128 (one per 4 floats).
// Row j (128 floats) = 32 consecutive ulonglong2 elements.
__constant__ ulonglong2 cW2v[4096];

__device__ __forceinline__ unsigned long long fma2(unsigned long long a,
                                                   unsigned long long b,
                                                   unsigned long long c) {
    unsigned long long d;
    asm("fma.rn.f32x2 %0, %1, %2, %3;" : "=l"(d) : "l"(a), "l"(b), "l"(c));
    return d;
}
__device__ __forceinline__ float lo32(unsigned long long a) {
    return __uint_as_float((unsigned)(a & 0xffffffffull));
}
__device__ __forceinline__ float hi32(unsigned long long a) {
    return __uint_as_float((unsigned)(a >> 32));
}
__device__ __forceinline__ float softplusf(float x) {
    return fmaxf(x, 0.0f) + log1pf(expf(-fabsf(x)));
}

// Shared-memory word offsets (floats). 128 samples / block, 512 threads.
// pb (spline params, 128*48 = 6144) ALIASES h1 (dead after GEMM2).
#define OFF_H1   0        // 32*514 = 16448
#define OFF_PB   0        // aliases h1
#define OFF_H2   16448    // 16448
#define OFF_W3   32896    // 48*128 = 6144
#define OFF_W1   39040    // 384
#define OFF_B1   39424    // 128
#define OFF_B2   39552    // 128
#define OFF_B3   39680    // 48
#define OFF_XS   39728    // 512
#define OFF_CS   40240    // 128
#define OFF_LAD  40368    // 256
#define OFF_LDT  40624    // 128
#define SMEM_FLOATS 40752 // 163,008 bytes

template<int MI0, int MI1, int I0, int I1, bool FIRST>
__global__ __launch_bounds__(512)
void rqs_layer_kernel(const float* __restrict__ xin,
                      const float* __restrict__ cond,
                      const float* __restrict__ W1l, const float* __restrict__ b1l,
                      const float* __restrict__ b2l,
                      const float* __restrict__ W3l, const float* __restrict__ b3l,
                      float* __restrict__ xout, float* __restrict__ ld)
{
    extern __shared__ float sm[];
    float* h1  = sm + OFF_H1;
    float* h2  = sm + OFF_H2;
    float* sW3 = sm + OFF_W3;
    float* sW1 = sm + OFF_W1;
    float* sb1 = sm + OFF_B1;
    float* sb2 = sm + OFF_B2;
    float* sb3 = sm + OFF_B3;
    float* xs  = sm + OFF_XS;
    float* cs  = sm + OFF_CS;
    float* pb  = sm + OFF_PB;
    float* lad = sm + OFF_LAD;
    float* ldt = sm + OFF_LDT;

    const int t = threadIdx.x;
    const int base = blockIdx.x * 128;

    // per-block inputs (512 threads = 128 samples * 4)
    xs[t] = xin[base * 4 + t];
    if (t < 128) {
        cs[t] = cond[base + t];
        ldt[t] = FIRST ? 0.0f : ld[base + t];
    }

    // stage small weights (W3, W1, biases) into smem
    {
        const float4* w3p = (const float4*)W3l;   // 1472 float4 (46*128 floats)
        float4* dW3 = (float4*)sW3;
        #pragma unroll
        for (int i = 0; i < 3; i++) {
            int idx = t + i * 512;
            if (idx < 1472) dW3[idx] = w3p[idx];
        }
        if (t < 64) dW3[1472 + t] = make_float4(0.f, 0.f, 0.f, 0.f);

        if (t < 96) ((float4*)sW1)[t] = ((const float4*)W1l)[t];
        if (t < 128) { sb1[t] = b1l[t]; sb2[t] = b2l[t]; }
        if (t < 48) sb3[t] = (t < 46) ? b3l[t] : 0.0f;
    }
    __syncthreads();

    const int sg = t & 31;   // sample group: samples 4*sg .. 4*sg+3
    const int g  = t >> 5;   // output group 0..15 (uniform per warp)

    // ---- layer 1: h1 = relu([x_m0, x_m1, cond] @ W1^T + b1) ----
    {
        #pragma unroll
        for (int i = 0; i < 32; i++) {
            int idx = t + i * 512;
            int s = idx >> 7, h = idx & 127;
            float m0 = xs[s * 4 + MI0], m1 = xs[s * 4 + MI1], m2 = cs[s];
            float r = fmaf(sW1[h * 3], m0,
                      fmaf(sW1[h * 3 + 1], m1,
                      fmaf(sW1[h * 3 + 2], m2, sb1[h])));
            h1[(s >> 2) * 514 + (h >> 1) * 8 + (s & 3) * 2 + (h & 1)] = fmaxf(r, 0.0f);
        }
    }
    __syncthreads();

    // ---- GEMM2: h2 = relu(h1 @ W2^T + b2); W2 from constant bank,
    //      h from smem. Per-accumulator k-order is ascending pairs ->
    //      bitwise identical to the passing R5 kernel. ----
    {
        const float* hb = h1 + sg * 514;
        const ulonglong2* wrow = cW2v + (g * 8) * 32;  // 128 floats = 32 ull2 / row
        unsigned long long acc[8][4];
        #pragma unroll
        for (int jj = 0; jj < 8; jj++)
            #pragma unroll
            for (int si = 0; si < 4; si++) acc[jj][si] = 0ull;

        #pragma unroll 2
        for (int kq = 0; kq < 32; kq++) {        // kq covers 4 k-values (2 pairs)
            unsigned long long hv0[4], hv1[4];
            #pragma unroll
            for (int si = 0; si < 4; si++) {
                hv0[si] = *(const unsigned long long*)(hb + kq * 16 + si * 2);
                hv1[si] = *(const unsigned long long*)(hb + kq * 16 + 8 + si * 2);
            }
            #pragma unroll
            for (int jj = 0; jj < 8; jj++) {
                ulonglong2 w = wrow[jj * 32 + kq];   // floats 4kq .. 4kq+3 of row
                #pragma unroll
                for (int si = 0; si < 4; si++) {
                    acc[jj][si] = fma2(w.x, hv0[si], acc[jj][si]);
                    acc[jj][si] = fma2(w.y, hv1[si], acc[jj][si]);
                }
            }
        }
        #pragma unroll
        for (int jj = 0; jj < 8; jj++) {
            int j = g * 8 + jj;
            float bb = sb2[j];
            #pragma unroll
            for (int si = 0; si < 4; si++) {
                float r = lo32(acc[jj][si]) + hi32(acc[jj][si]) + bb;
                h2[sg * 514 + (j >> 1) * 8 + si * 2 + (j & 1)] = fmaxf(r, 0.0f);
            }
        }
    }
    __syncthreads();

    // ---- GEMM3: params = h2 @ W3^T + b3 (48 outputs, rows 46/47 zero) ----
    // writes pb, which aliases h1 (h1 dead after GEMM2; barrier above).
    {
        const float* hb = h2 + sg * 514;
        const float* wb = sW3 + (g * 3) * 128;
        unsigned long long acc[3][4];
        #pragma unroll
        for (int jj = 0; jj < 3; jj++)
            #pragma unroll
            for (int si = 0; si < 4; si++) acc[jj][si] = 0ull;

        #pragma unroll 4
        for (int kp = 0; kp < 64; kp++) {
            unsigned long long hv0 = *(const unsigned long long*)(hb + kp * 8);
            unsigned long long hv1 = *(const unsigned long long*)(hb + kp * 8 + 2);
            unsigned long long hv2 = *(const unsigned long long*)(hb + kp * 8 + 4);
            unsigned long long hv3 = *(const unsigned long long*)(hb + kp * 8 + 6);
            #pragma unroll
            for (int jj = 0; jj < 3; jj++) {
                unsigned long long wv =
                    *(const unsigned long long*)(wb + jj * 128 + kp * 2);
                acc[jj][0] = fma2(wv, hv0, acc[jj][0]);
                acc[jj][1] = fma2(wv, hv1, acc[jj][1]);
                acc[jj][2] = fma2(wv, hv2, acc[jj][2]);
                acc[jj][3] = fma2(wv, hv3, acc[jj][3]);
            }
        }
        #pragma unroll
        for (int jj = 0; jj < 3; jj++) {
            int j = g * 3 + jj;
            float bb = sb3[j];
            #pragma unroll
            for (int si = 0; si < 4; si++) {
                pb[(sg * 4 + si) * 48 + j] =
                    lo32(acc[jj][si]) + hi32(acc[jj][si]) + bb;
            }
        }
    }
    __syncthreads();

    // ---- RQS spline: one thread per (sample, transformed-dim) ----
    if (t < 256) {
        const int s = t >> 1, f = t & 1;
        const int ii = f ? I1 : I0;
        const float* pp = pb + s * 48 + f;

        float uw[8];
        #pragma unroll
        for (int j = 0; j < 8; j++) uw[j] = pp[2 * j];
        float mw = uw[0];
        #pragma unroll
        for (int j = 1; j < 8; j++) mw = fmaxf(mw, uw[j]);
        float ew[8], swsum = 0.0f;
        #pragma unroll
        for (int j = 0; j < 8; j++) { ew[j] = expf(uw[j] - mw); swsum += ew[j]; }
        float scw = (1.0f - MIN_BW * 8.0f) / swsum;
        float cw[9];
        cw[0] = -TAILB;
        {
            float c = 0.0f;
            #pragma unroll
            for (int j = 0; j < 8; j++) {
                c += MIN_BW + scw * ew[j];
                cw[j + 1] = fmaf(2.0f * TAILB, c, -TAILB);
            }
        }
        cw[8] = TAILB;

        float uh[8];
        #pragma unroll
        for (int j = 0; j < 8; j++) uh[j] = pp[2 * (8 + j)];
        float mh = uh[0];
        #pragma unroll
        for (int j = 1; j < 8; j++) mh = fmaxf(mh, uh[j]);
        float eh[8], shsum = 0.0f;
        #pragma unroll
        for (int j = 0; j < 8; j++) { eh[j] = expf(uh[j] - mh); shsum += eh[j]; }
        float sch = (1.0f - MIN_BH * 8.0f) / shsum;
        float ch[9];
        ch[0] = -TAILB;
        {
            float c = 0.0f;
            #pragma unroll
            for (int j = 0; j < 8; j++) {
                c += MIN_BH + sch * eh[j];
                ch[j + 1] = fmaf(2.0f * TAILB, c, -TAILB);
            }
        }
        ch[8] = TAILB;

        float dv[9];
        dv[0] = 1.0f; dv[8] = 1.0f;
        #pragma unroll
        for (int j = 0; j < 7; j++)
            dv[j + 1] = MIN_DD + softplusf(pp[2 * (16 + j)]);

        float xv = xs[s * 4 + ii];
        bool inside = (xv >= -TAILB) && (xv <= TAILB);
        float xc = fminf(fmaxf(xv, -TAILB), TAILB);

        int bin = 0;
        #pragma unroll
        for (int i = 1; i < 8; i++) if (xc >= cw[i]) bin = i;

        float icw = cw[0], iw = cw[1] - cw[0];
        float ich = ch[0], ih = ch[1] - ch[0];
        float dk = dv[0], dk1 = dv[1];
        #pragma unroll
        for (int i = 1; i < 8; i++) if (bin == i) {
            icw = cw[i]; iw = cw[i + 1] - cw[i];
            ich = ch[i]; ih = ch[i + 1] - ch[i];
            dk = dv[i]; dk1 = dv[i + 1];
        }

        float th = (xc - icw) / iw;
        float delta = ih / iw;
        float omt = 1.0f - th;
        float tomt = th * omt;
        float num = ih * (delta * th * th + dk * tomt);
        float den = delta + (dk + dk1 - 2.0f * delta) * tomt;
        float y = ich + num / den;
        float dnum = delta * delta *
                     (dk1 * th * th + 2.0f * delta * tomt + dk * omt * omt);
        float ladv = logf(dnum) - 2.0f * logf(den);

        xs[s * 4 + ii] = inside ? y : xv;
        lad[t] = inside ? ladv : 0.0f;
    }
    __syncthreads();

    // write back per-layer state
    xout[base * 4 + t] = xs[t];
    if (t < 128) ld[base + t] = ldt[t] + lad[2 * t] + lad[2 * t + 1];
}

extern "C" void kernel_launch(void* const* d_in, const int* in_sizes, int n_in,
                              void* d_out, int out_size)
{
    const float* inputs = (const float*)d_in[0];
    const float* cond   = (const float*)d_in[1];
    const float* W1     = (const float*)d_in[2];
    const float* b1     = (const float*)d_in[3];
    const float* W2     = (const float*)d_in[4];
    const float* b2     = (const float*)d_in[5];
    const float* W3     = (const float*)d_in[6];
    const float* b3     = (const float*)d_in[7];
    float* out = (float*)d_out;

    const int B = in_sizes[0] / 4;
    float* out_x  = out;                      // [B,4] evolving state
    float* out_ld = out + (size_t)B * 4;      // [B] logdets
    const int grid = B / 128;
    const int smem_bytes = SMEM_FLOATS * 4;   // 163,008 bytes

    // unconditional (no static guards) — idempotent, capture-safe
    cudaFuncSetAttribute(rqs_layer_kernel<0,2,1,3,true>,
                         cudaFuncAttributeMaxDynamicSharedMemorySize, smem_bytes);
    cudaFuncSetAttribute(rqs_layer_kernel<1,3,0,2,false>,
                         cudaFuncAttributeMaxDynamicSharedMemorySize, smem_bytes);
    cudaFuncSetAttribute(rqs_layer_kernel<0,1,2,3,false>,
                         cudaFuncAttributeMaxDynamicSharedMemorySize, smem_bytes);
    cudaFuncSetAttribute(rqs_layer_kernel<2,3,0,1,false>,
                         cudaFuncAttributeMaxDynamicSharedMemorySize, smem_bytes);

    // layer 0 (reads harness input, initializes logdets)
    cudaMemcpyToSymbolAsync(cW2v, W2 + 0 * 16384, 65536, 0,
                            cudaMemcpyDeviceToDevice, 0);
    rqs_layer_kernel<0,2,1,3,true><<<grid, 512, smem_bytes>>>(
        inputs, cond, W1 + 0 * 384, b1 + 0 * 128, b2 + 0 * 128,
        W3 + 0 * 5888, b3 + 0 * 46, out_x, out_ld);

    // layer 1
    cudaMemcpyToSymbolAsync(cW2v, W2 + 1 * 16384, 65536, 0,
                            cudaMemcpyDeviceToDevice, 0);
    rqs_layer_kernel<1,3,0,2,false><<<grid, 512, smem_bytes>>>(
        out_x, cond, W1 + 1 * 384, b1 + 1 * 128, b2 + 1 * 128,
        W3 + 1 * 5888, b3 + 1 * 46, out_x, out_ld);

    // layer 2
    cudaMemcpyToSymbolAsync(cW2v, W2 + 2 * 16384, 65536, 0,
                            cudaMemcpyDeviceToDevice, 0);
    rqs_layer_kernel<0,1,2,3,false><<<grid, 512, smem_bytes>>>(
        out_x, cond, W1 + 2 * 384, b1 + 2 * 128, b2 + 2 * 128,
        W3 + 2 * 5888, b3 + 2 * 46, out_x, out_ld);

    // layer 3
    cudaMemcpyToSymbolAsync(cW2v, W2 + 3 * 16384, 65536, 0,
                            cudaMemcpyDeviceToDevice, 0);
    rqs_layer_kernel<2,3,0,1,false><<<grid, 512, smem_bytes>>>(
        out_x, cond, W1 + 3 * 384, b1 + 3 * 128, b2 + 3 * 128,
        W3 + 3 * 5888, b3 + 3 * 46, out_x, out_ld);
}

// round 9
// speedup vs baseline: 6.0672x; 6.0672x over previous
#include <cuda_runtime.h>

#define TAILB 12.0f
#define MIN_BW 1e-6f
#define MIN_BH 1e-6f
#define MIN_DD 1e-6f

// layer index tables
__device__ __constant__ int MI0c[4] = {0, 1, 0, 2};
__device__ __constant__ int MI1c[4] = {2, 3, 1, 3};
__device__ __constant__ int II0c[4] = {1, 0, 2, 0};
__device__ __constant__ int II1c[4] = {3, 2, 3, 1};

__device__ __forceinline__ unsigned long long fma2(unsigned long long a,
                                                   unsigned long long b,
                                                   unsigned long long c) {
    unsigned long long d;
    asm("fma.rn.f32x2 %0, %1, %2, %3;" : "=l"(d) : "l"(a), "l"(b), "l"(c));
    return d;
}
__device__ __forceinline__ float lo32(unsigned long long a) {
    return __uint_as_float((unsigned)(a & 0xffffffffull));
}
__device__ __forceinline__ float hi32(unsigned long long a) {
    return __uint_as_float((unsigned)(a >> 32));
}
__device__ __forceinline__ float softplusf(float x) {
    return fmaxf(x, 0.0f) + log1pf(expf(-fabsf(x)));
}

// Shared-memory word offsets (floats). 128 samples / block, 256 threads.
// h layout: 16 rows of 8 samples, row stride 1026 words (bank-conflict-free:
// 1026 mod 32 = 2, even => LDS.64 aligned; q*1026 hits 16 distinct banks).
// Element (s, k): h[(s>>3)*1026 + (k>>1)*16 + (s&7)*2 + (k&1)].
// pb (spline params, 128*48 = 6144) ALIASES h1 (dead after GEMM2).
#define OFF_H1   0        // 16*1026 = 16416
#define OFF_PB   0        // aliases h1
#define OFF_H2   16416    // 16416
#define OFF_W2   32832    // 16384
#define OFF_W3   49216    // 48*128 = 6144
#define OFF_W1   55360    // 384
#define OFF_B1   55744    // 128
#define OFF_B2   55872    // 128
#define OFF_B3   56000    // 48
#define OFF_XS   56048    // 512
#define OFF_CS   56560    // 128
#define OFF_LAD  56688    // 256
#define OFF_LDT  56944    // 128
#define SMEM_FLOATS 57072 // 228,288 bytes

__global__ __launch_bounds__(256, 1)
void rqs_fused_kernel(const float* __restrict__ inputs,
                      const float* __restrict__ cond,
                      const float* __restrict__ W1, const float* __restrict__ b1,
                      const float* __restrict__ W2, const float* __restrict__ b2,
                      const float* __restrict__ W3, const float* __restrict__ b3,
                      float* __restrict__ out, int B)
{
    extern __shared__ float sm[];
    float* h1  = sm + OFF_H1;
    float* h2  = sm + OFF_H2;
    float* sW2 = sm + OFF_W2;
    float* sW3 = sm + OFF_W3;
    float* sW1 = sm + OFF_W1;
    float* sb1 = sm + OFF_B1;
    float* sb2 = sm + OFF_B2;
    float* sb3 = sm + OFF_B3;
    float* xs  = sm + OFF_XS;
    float* cs  = sm + OFF_CS;
    float* pb  = sm + OFF_PB;
    float* lad = sm + OFF_LAD;
    float* ldt = sm + OFF_LDT;

    const int t = threadIdx.x;
    const int base = blockIdx.x * 128;

    // per-block inputs (256 threads, 512 x-values, 128 cond/ld)
    xs[t]       = inputs[base * 4 + t];
    xs[t + 256] = inputs[base * 4 + t + 256];
    if (t < 128) { cs[t] = cond[base + t]; ldt[t] = 0.0f; }

    const int q  = t & 15;   // sample row: samples 8q .. 8q+7
    const int g  = t >> 4;   // output group 0..15

    #pragma unroll 1
    for (int l = 0; l < 4; l++) {
        __syncthreads();
        // ---- stage layer weights into smem ----
        {
            const float4* w2p = (const float4*)(W2 + l * 16384);
            float4* dW2 = (float4*)sW2;
            #pragma unroll
            for (int i = 0; i < 16; i++) dW2[t + i * 256] = w2p[t + i * 256];

            const float4* w3p = (const float4*)(W3 + l * 5888);
            float4* dW3 = (float4*)sW3;
            #pragma unroll
            for (int i = 0; i < 6; i++) {
                int idx = t + i * 256;
                if (idx < 1472) dW3[idx] = w3p[idx];
            }
            if (t < 64) dW3[1472 + t] = make_float4(0.f, 0.f, 0.f, 0.f);

            if (t < 96) ((float4*)sW1)[t] = ((const float4*)(W1 + l * 384))[t];
            if (t < 128) { sb1[t] = b1[l * 128 + t]; sb2[t] = b2[l * 128 + t]; }
            if (t < 48) sb3[t] = (t < 46) ? b3[l * 46 + t] : 0.0f;
        }
        __syncthreads();

        // ---- layer 1: h1 = relu([x_m0, x_m1, cond] @ W1^T + b1) ----
        {
            const int mi0 = MI0c[l], mi1 = MI1c[l];
            #pragma unroll
            for (int i = 0; i < 64; i++) {
                int idx = t + i * 256;
                int s = idx >> 7, h = idx & 127;
                float m0 = xs[s * 4 + mi0], m1 = xs[s * 4 + mi1], m2 = cs[s];
                float r = fmaf(sW1[h * 3], m0,
                          fmaf(sW1[h * 3 + 1], m1,
                          fmaf(sW1[h * 3 + 2], m2, sb1[h])));
                h1[(s >> 3) * 1026 + (h >> 1) * 16 + (s & 7) * 2 + (h & 1)] =
                    fmaxf(r, 0.0f);
            }
        }
        __syncthreads();

        // ---- GEMM2: h2 = relu(h1 @ W2^T + b2), 8 samples x 8 outs / thread.
        //      Per-(s,j) k-order = ascending pairs (bitwise identical). ----
        {
            const float* hb = h1 + q * 1026;
            const float* wb = sW2 + (g * 8) * 128;
            unsigned long long acc[8][8];
            #pragma unroll
            for (int jj = 0; jj < 8; jj++)
                #pragma unroll
                for (int ss = 0; ss < 8; ss++) acc[jj][ss] = 0ull;

            #pragma unroll 1
            for (int kp = 0; kp < 64; kp++) {
                unsigned long long hv[8];
                #pragma unroll
                for (int ss = 0; ss < 8; ss++)
                    hv[ss] = *(const unsigned long long*)(hb + kp * 16 + ss * 2);
                #pragma unroll
                for (int jj = 0; jj < 8; jj++) {
                    unsigned long long wv =
                        *(const unsigned long long*)(wb + jj * 128 + kp * 2);
                    #pragma unroll
                    for (int ss = 0; ss < 8; ss++)
                        acc[jj][ss] = fma2(wv, hv[ss], acc[jj][ss]);
                }
            }
            #pragma unroll
            for (int jj = 0; jj < 8; jj++) {
                int j = g * 8 + jj;
                float bb = sb2[j];
                #pragma unroll
                for (int ss = 0; ss < 8; ss++) {
                    float r = lo32(acc[jj][ss]) + hi32(acc[jj][ss]) + bb;
                    h2[q * 1026 + (j >> 1) * 16 + ss * 2 + (j & 1)] =
                        fmaxf(r, 0.0f);
                }
            }
        }
        __syncthreads();

        // ---- GEMM3: params = h2 @ W3^T + b3 (48 outs, rows 46/47 zero),
        //      8 samples x 3 outs / thread. Writes pb (aliases h1). ----
        {
            const float* hb = h2 + q * 1026;
            const float* wb = sW3 + (g * 3) * 128;
            unsigned long long acc[3][8];
            #pragma unroll
            for (int jj = 0; jj < 3; jj++)
                #pragma unroll
                for (int ss = 0; ss < 8; ss++) acc[jj][ss] = 0ull;

            #pragma unroll 2
            for (int kp = 0; kp < 64; kp++) {
                unsigned long long hv[8];
                #pragma unroll
                for (int ss = 0; ss < 8; ss++)
                    hv[ss] = *(const unsigned long long*)(hb + kp * 16 + ss * 2);
                #pragma unroll
                for (int jj = 0; jj < 3; jj++) {
                    unsigned long long wv =
                        *(const unsigned long long*)(wb + jj * 128 + kp * 2);
                    #pragma unroll
                    for (int ss = 0; ss < 8; ss++)
                        acc[jj][ss] = fma2(wv, hv[ss], acc[jj][ss]);
                }
            }
            #pragma unroll
            for (int jj = 0; jj < 3; jj++) {
                int j = g * 3 + jj;
                float bb = sb3[j];
                #pragma unroll
                for (int ss = 0; ss < 8; ss++) {
                    pb[(q * 8 + ss) * 48 + j] =
                        lo32(acc[jj][ss]) + hi32(acc[jj][ss]) + bb;
                }
            }
        }
        __syncthreads();

        // ---- RQS spline: one thread per (sample, transformed-dim) ----
        {
            const int s = t >> 1, f = t & 1;
            const int ii = f ? II1c[l] : II0c[l];
            const float* pp = pb + s * 48 + f;

            float uw[8];
            #pragma unroll
            for (int j = 0; j < 8; j++) uw[j] = pp[2 * j];
            float mw = uw[0];
            #pragma unroll
            for (int j = 1; j < 8; j++) mw = fmaxf(mw, uw[j]);
            float ew[8], swsum = 0.0f;
            #pragma unroll
            for (int j = 0; j < 8; j++) { ew[j] = expf(uw[j] - mw); swsum += ew[j]; }
            float scw = (1.0f - MIN_BW * 8.0f) / swsum;
            float cw[9];
            cw[0] = -TAILB;
            {
                float c = 0.0f;
                #pragma unroll
                for (int j = 0; j < 8; j++) {
                    c += MIN_BW + scw * ew[j];
                    cw[j + 1] = fmaf(2.0f * TAILB, c, -TAILB);
                }
            }
            cw[8] = TAILB;

            float uh[8];
            #pragma unroll
            for (int j = 0; j < 8; j++) uh[j] = pp[2 * (8 + j)];
            float mh = uh[0];
            #pragma unroll
            for (int j = 1; j < 8; j++) mh = fmaxf(mh, uh[j]);
            float eh[8], shsum = 0.0f;
            #pragma unroll
            for (int j = 0; j < 8; j++) { eh[j] = expf(uh[j] - mh); shsum += eh[j]; }
            float sch = (1.0f - MIN_BH * 8.0f) / shsum;
            float ch[9];
            ch[0] = -TAILB;
            {
                float c = 0.0f;
                #pragma unroll
                for (int j = 0; j < 8; j++) {
                    c += MIN_BH + sch * eh[j];
                    ch[j + 1] = fmaf(2.0f * TAILB, c, -TAILB);
                }
            }
            ch[8] = TAILB;

            float dv[9];
            dv[0] = 1.0f; dv[8] = 1.0f;
            #pragma unroll
            for (int j = 0; j < 7; j++)
                dv[j + 1] = MIN_DD + softplusf(pp[2 * (16 + j)]);

            float xv = xs[s * 4 + ii];
            bool inside = (xv >= -TAILB) && (xv <= TAILB);
            float xc = fminf(fmaxf(xv, -TAILB), TAILB);

            int bin = 0;
            #pragma unroll
            for (int i = 1; i < 8; i++) if (xc >= cw[i]) bin = i;

            float icw = cw[0], iw = cw[1] - cw[0];
            float ich = ch[0], ih = ch[1] - ch[0];
            float dk = dv[0], dk1 = dv[1];
            #pragma unroll
            for (int i = 1; i < 8; i++) if (bin == i) {
                icw = cw[i]; iw = cw[i + 1] - cw[i];
                ich = ch[i]; ih = ch[i + 1] - ch[i];
                dk = dv[i]; dk1 = dv[i + 1];
            }

            float th = (xc - icw) / iw;
            float delta = ih / iw;
            float omt = 1.0f - th;
            float tomt = th * omt;
            float num = ih * (delta * th * th + dk * tomt);
            float den = delta + (dk + dk1 - 2.0f * delta) * tomt;
            float y = ich + num / den;
            float dnum = delta * delta *
                         (dk1 * th * th + 2.0f * delta * tomt + dk * omt * omt);
            float ladv = logf(dnum) - 2.0f * logf(den);

            xs[s * 4 + ii] = inside ? y : xv;
            lad[t] = inside ? ladv : 0.0f;
        }
        __syncthreads();
        if (t < 128) ldt[t] += lad[2 * t] + lad[2 * t + 1];
    }

    __syncthreads();
    // outputs: x flattened [B,4] then logdets [B,1]
    out[base * 4 + t]       = xs[t];
    out[base * 4 + t + 256] = xs[t + 256];
    if (t < 128) out[(size_t)B * 4 + base + t] = ldt[t];
}

extern "C" void kernel_launch(void* const* d_in, const int* in_sizes, int n_in,
                              void* d_out, int out_size)
{
    const float* inputs = (const float*)d_in[0];
    const float* cond   = (const float*)d_in[1];
    const float* W1     = (const float*)d_in[2];
    const float* b1     = (const float*)d_in[3];
    const float* W2     = (const float*)d_in[4];
    const float* b2     = (const float*)d_in[5];
    const float* W3     = (const float*)d_in[6];
    const float* b3     = (const float*)d_in[7];
    float* out = (float*)d_out;

    const int B = in_sizes[0] / 4;
    const int smem_bytes = SMEM_FLOATS * 4;  // 228,288 bytes
    cudaFuncSetAttribute(rqs_fused_kernel,
                         cudaFuncAttributeMaxDynamicSharedMemorySize, smem_bytes);
    rqs_fused_kernel<<<B / 128, 256, smem_bytes>>>(inputs, cond, W1, b1, W2, b2,
                                                   W3, b3, out, B);
}

// round 10
// speedup vs baseline: 6.2205x; 1.0253x over previous
#include <cuda_runtime.h>

#define TAILB 12.0f
#define MIN_BW 1e-6f
#define MIN_BH 1e-6f
#define MIN_DD 1e-6f

// layer index tables
__device__ __constant__ int MI0c[4] = {0, 1, 0, 2};
__device__ __constant__ int MI1c[4] = {2, 3, 1, 3};
__device__ __constant__ int II0c[4] = {1, 0, 2, 0};
__device__ __constant__ int II1c[4] = {3, 2, 3, 1};

__device__ __forceinline__ unsigned long long fma2(unsigned long long a,
                                                   unsigned long long b,
                                                   unsigned long long c) {
    unsigned long long d;
    asm("fma.rn.f32x2 %0, %1, %2, %3;" : "=l"(d) : "l"(a), "l"(b), "l"(c));
    return d;
}
__device__ __forceinline__ float lo32(unsigned long long a) {
    return __uint_as_float((unsigned)(a & 0xffffffffull));
}
__device__ __forceinline__ float hi32(unsigned long long a) {
    return __uint_as_float((unsigned)(a >> 32));
}
__device__ __forceinline__ float softplusf(float x) {
    return fmaxf(x, 0.0f) + log1pf(expf(-fabsf(x)));
}

// Shared memory (floats). 128 samples / block, 256 threads.
// h layout (4-k-contiguous, LDS.128-friendly): 16 rows of 8 samples,
// row stride 1028 (mod 32 = 4 => 16 sample-rows spread over 8 bank-quads).
// Element (s, k): h[(s>>3)*1028 + (k>>2)*32 + (s&7)*4 + (k&3)].
// pb (spline params, stride 50 => conflict-free spline reads) ALIASES h1.
#define OFF_H1   0        // 16*1028 = 16448
#define OFF_PB   0        // aliases h1 (128*50 = 6400 <= 16448)
#define OFF_H2   16448    // 16448
#define OFF_W2   32896    // 16384
#define OFF_W3   49280    // 48*128 = 6144
#define OFF_W1   55424    // 384
#define OFF_B1   55808    // 128
#define OFF_B2   55936    // 128
#define OFF_B3   56064    // 48
#define OFF_XS   56112    // 512
#define OFF_CS   56624    // 128
#define OFF_LAD  56752    // 256
#define OFF_LDT  57008    // 128
#define SMEM_FLOATS 57136 // 228,544 bytes

__global__ __launch_bounds__(256, 1)
void rqs_fused_kernel(const float* __restrict__ inputs,
                      const float* __restrict__ cond,
                      const float* __restrict__ W1, const float* __restrict__ b1,
                      const float* __restrict__ W2, const float* __restrict__ b2,
                      const float* __restrict__ W3, const float* __restrict__ b3,
                      float* __restrict__ out, int B)
{
    extern __shared__ float sm[];
    float* h1  = sm + OFF_H1;
    float* h2  = sm + OFF_H2;
    float* sW2 = sm + OFF_W2;
    float* sW3 = sm + OFF_W3;
    float* sW1 = sm + OFF_W1;
    float* sb1 = sm + OFF_B1;
    float* sb2 = sm + OFF_B2;
    float* sb3 = sm + OFF_B3;
    float* xs  = sm + OFF_XS;
    float* cs  = sm + OFF_CS;
    float* pb  = sm + OFF_PB;
    float* lad = sm + OFF_LAD;
    float* ldt = sm + OFF_LDT;

    const int t = threadIdx.x;
    const int base = blockIdx.x * 128;

    xs[t]       = inputs[base * 4 + t];
    xs[t + 256] = inputs[base * 4 + t + 256];
    if (t < 128) { cs[t] = cond[base + t]; ldt[t] = 0.0f; }

    const int q  = t & 15;   // sample row: samples 8q .. 8q+7
    const int g  = t >> 4;   // output group 0..15

    #pragma unroll 1
    for (int l = 0; l < 4; l++) {
        __syncthreads();
        // ---- stage layer weights into smem ----
        {
            const float4* w2p = (const float4*)(W2 + l * 16384);
            float4* dW2 = (float4*)sW2;
            #pragma unroll
            for (int i = 0; i < 16; i++) dW2[t + i * 256] = w2p[t + i * 256];

            const float4* w3p = (const float4*)(W3 + l * 5888);
            float4* dW3 = (float4*)sW3;
            #pragma unroll
            for (int i = 0; i < 6; i++) {
                int idx = t + i * 256;
                if (idx < 1472) dW3[idx] = w3p[idx];
            }
            if (t < 64) dW3[1472 + t] = make_float4(0.f, 0.f, 0.f, 0.f);

            if (t < 96) ((float4*)sW1)[t] = ((const float4*)(W1 + l * 384))[t];
            if (t < 128) { sb1[t] = b1[l * 128 + t]; sb2[t] = b2[l * 128 + t]; }
            if (t < 48) sb3[t] = (t < 46) ? b3[l * 46 + t] : 0.0f;
        }
        __syncthreads();

        // ---- layer 1: h1 = relu([x_m0, x_m1, cond] @ W1^T + b1) ----
        // thread computes h-pair (2p, 2p+1) for sample s; STS.64 store.
        {
            const int mi0 = MI0c[l], mi1 = MI1c[l];
            #pragma unroll
            for (int i = 0; i < 32; i++) {
                int idx = t + i * 256;          // 128 samples * 64 h-pairs
                int s = idx >> 6, p = idx & 63; // h = 2p, 2p+1
                float m0 = xs[s * 4 + mi0], m1 = xs[s * 4 + mi1], m2 = cs[s];
                int h0 = 2 * p;
                float r0 = fmaf(sW1[h0 * 3], m0,
                           fmaf(sW1[h0 * 3 + 1], m1,
                           fmaf(sW1[h0 * 3 + 2], m2, sb1[h0])));
                float r1 = fmaf(sW1[h0 * 3 + 3], m0,
                           fmaf(sW1[h0 * 3 + 4], m1,
                           fmaf(sW1[h0 * 3 + 5], m2, sb1[h0 + 1])));
                float2 v = make_float2(fmaxf(r0, 0.0f), fmaxf(r1, 0.0f));
                *(float2*)(h1 + (s >> 3) * 1028 + (p >> 1) * 32 +
                           (s & 7) * 4 + (p & 1) * 2) = v;
            }
        }
        __syncthreads();

        // ---- GEMM2: h2 = relu(h1 @ W2^T + b2), 8 samples x 8 outs/thread.
        //      LDS.128 loads (4 k at a time); per-acc k-order ascending
        //      (bitwise identical). ----
        {
            const float* hb = h1 + q * 1028;
            const float* wb = sW2 + (g * 8) * 128;
            unsigned long long acc[8][8];
            #pragma unroll
            for (int jj = 0; jj < 8; jj++)
                #pragma unroll
                for (int ss = 0; ss < 8; ss++) acc[jj][ss] = 0ull;

            #pragma unroll 1
            for (int kq = 0; kq < 32; kq++) {     // kq = 4 k-values
                ulonglong2 hv[8];
                #pragma unroll
                for (int ss = 0; ss < 8; ss++)
                    hv[ss] = *(const ulonglong2*)(hb + kq * 32 + ss * 4);
                #pragma unroll
                for (int jj = 0; jj < 8; jj++) {
                    ulonglong2 w = *(const ulonglong2*)(wb + jj * 128 + kq * 4);
                    #pragma unroll
                    for (int ss = 0; ss < 8; ss++) {
                        acc[jj][ss] = fma2(w.x, hv[ss].x, acc[jj][ss]);
                        acc[jj][ss] = fma2(w.y, hv[ss].y, acc[jj][ss]);
                    }
                }
            }
            // epilogue: STS.128, thread owns j = g*8 .. g*8+7 (two k-quads)
            #pragma unroll
            for (int ss = 0; ss < 8; ss++) {
                float4 v0, v1;
                v0.x = fmaxf(lo32(acc[0][ss]) + hi32(acc[0][ss]) + sb2[g*8+0], 0.f);
                v0.y = fmaxf(lo32(acc[1][ss]) + hi32(acc[1][ss]) + sb2[g*8+1], 0.f);
                v0.z = fmaxf(lo32(acc[2][ss]) + hi32(acc[2][ss]) + sb2[g*8+2], 0.f);
                v0.w = fmaxf(lo32(acc[3][ss]) + hi32(acc[3][ss]) + sb2[g*8+3], 0.f);
                v1.x = fmaxf(lo32(acc[4][ss]) + hi32(acc[4][ss]) + sb2[g*8+4], 0.f);
                v1.y = fmaxf(lo32(acc[5][ss]) + hi32(acc[5][ss]) + sb2[g*8+5], 0.f);
                v1.z = fmaxf(lo32(acc[6][ss]) + hi32(acc[6][ss]) + sb2[g*8+6], 0.f);
                v1.w = fmaxf(lo32(acc[7][ss]) + hi32(acc[7][ss]) + sb2[g*8+7], 0.f);
                *(float4*)(h2 + q * 1028 + (g * 2) * 32 + ss * 4) = v0;
                *(float4*)(h2 + q * 1028 + (g * 2 + 1) * 32 + ss * 4) = v1;
            }
        }
        __syncthreads();

        // ---- GEMM3: params = h2 @ W3^T + b3 (48 outs, rows 46/47 zero),
        //      8 samples x 3 outs / thread. Writes pb (aliases h1). ----
        {
            const float* hb = h2 + q * 1028;
            const float* wb = sW3 + (g * 3) * 128;
            unsigned long long acc[3][8];
            #pragma unroll
            for (int jj = 0; jj < 3; jj++)
                #pragma unroll
                for (int ss = 0; ss < 8; ss++) acc[jj][ss] = 0ull;

            #pragma unroll 1
            for (int kq = 0; kq < 32; kq++) {
                ulonglong2 hv[8];
                #pragma unroll
                for (int ss = 0; ss < 8; ss++)
                    hv[ss] = *(const ulonglong2*)(hb + kq * 32 + ss * 4);
                #pragma unroll
                for (int jj = 0; jj < 3; jj++) {
                    ulonglong2 w = *(const ulonglong2*)(wb + jj * 128 + kq * 4);
                    #pragma unroll
                    for (int ss = 0; ss < 8; ss++) {
                        acc[jj][ss] = fma2(w.x, hv[ss].x, acc[jj][ss]);
                        acc[jj][ss] = fma2(w.y, hv[ss].y, acc[jj][ss]);
                    }
                }
            }
            #pragma unroll
            for (int jj = 0; jj < 3; jj++) {
                int j = g * 3 + jj;
                float bb = sb3[j];
                #pragma unroll
                for (int ss = 0; ss < 8; ss++) {
                    pb[(q * 8 + ss) * 50 + j] =
                        lo32(acc[jj][ss]) + hi32(acc[jj][ss]) + bb;
                }
            }
        }
        __syncthreads();

        // ---- RQS spline: one thread per (sample, transformed-dim) ----
        {
            const int s = t >> 1, f = t & 1;
            const int ii = f ? II1c[l] : II0c[l];
            const float* pp = pb + s * 50 + f;

            float uw[8];
            #pragma unroll
            for (int j = 0; j < 8; j++) uw[j] = pp[2 * j];
            float mw = uw[0];
            #pragma unroll
            for (int j = 1; j < 8; j++) mw = fmaxf(mw, uw[j]);
            float ew[8], swsum = 0.0f;
            #pragma unroll
            for (int j = 0; j < 8; j++) { ew[j] = expf(uw[j] - mw); swsum += ew[j]; }
            float scw = (1.0f - MIN_BW * 8.0f) / swsum;
            float cw[9];
            cw[0] = -TAILB;
            {
                float c = 0.0f;
                #pragma unroll
                for (int j = 0; j < 8; j++) {
                    c += MIN_BW + scw * ew[j];
                    cw[j + 1] = fmaf(2.0f * TAILB, c, -TAILB);
                }
            }
            cw[8] = TAILB;

            float uh[8];
            #pragma unroll
            for (int j = 0; j < 8; j++) uh[j] = pp[2 * (8 + j)];
            float mh = uh[0];
            #pragma unroll
            for (int j = 1; j < 8; j++) mh = fmaxf(mh, uh[j]);
            float eh[8], shsum = 0.0f;
            #pragma unroll
            for (int j = 0; j < 8; j++) { eh[j] = expf(uh[j] - mh); shsum += eh[j]; }
            float sch = (1.0f - MIN_BH * 8.0f) / shsum;
            float ch[9];
            ch[0] = -TAILB;
            {
                float c = 0.0f;
                #pragma unroll
                for (int j = 0; j < 8; j++) {
                    c += MIN_BH + sch * eh[j];
                    ch[j + 1] = fmaf(2.0f * TAILB, c, -TAILB);
                }
            }
            ch[8] = TAILB;

            float dv[9];
            dv[0] = 1.0f; dv[8] = 1.0f;
            #pragma unroll
            for (int j = 0; j < 7; j++)
                dv[j + 1] = MIN_DD + softplusf(pp[2 * (16 + j)]);

            float xv = xs[s * 4 + ii];
            bool inside = (xv >= -TAILB) && (xv <= TAILB);
            float xc = fminf(fmaxf(xv, -TAILB), TAILB);

            int bin = 0;
            #pragma unroll
            for (int i = 1; i < 8; i++) if (xc >= cw[i]) bin = i;

            float icw = cw[0], iw = cw[1] - cw[0];
            float ich = ch[0], ih = ch[1] - ch[0];
            float dk = dv[0], dk1 = dv[1];
            #pragma unroll
            for (int i = 1; i < 8; i++) if (bin == i) {
                icw = cw[i]; iw = cw[i + 1] - cw[i];
                ich = ch[i]; ih = ch[i + 1] - ch[i];
                dk = dv[i]; dk1 = dv[i + 1];
            }

            float th = (xc - icw) / iw;
            float delta = ih / iw;
            float omt = 1.0f - th;
            float tomt = th * omt;
            float num = ih * (delta * th * th + dk * tomt);
            float den = delta + (dk + dk1 - 2.0f * delta) * tomt;
            float y = ich + num / den;
            float dnum = delta * delta *
                         (dk1 * th * th + 2.0f * delta * tomt + dk * omt * omt);
            float ladv = logf(dnum) - 2.0f * logf(den);

            xs[s * 4 + ii] = inside ? y : xv;
            lad[t] = inside ? ladv : 0.0f;
        }
        __syncthreads();
        if (t < 128) ldt[t] += lad[2 * t] + lad[2 * t + 1];
    }

    __syncthreads();
    // outputs: x flattened [B,4] then logdets [B,1]
    out[base * 4 + t]       = xs[t];
    out[base * 4 + t + 256] = xs[t + 256];
    if (t < 128) out[(size_t)B * 4 + base + t] = ldt[t];
}

extern "C" void kernel_launch(void* const* d_in, const int* in_sizes, int n_in,
                              void* d_out, int out_size)
{
    const float* inputs = (const float*)d_in[0];
    const float* cond   = (const float*)d_in[1];
    const float* W1     = (const float*)d_in[2];
    const float* b1     = (const float*)d_in[3];
    const float* W2     = (const float*)d_in[4];
    const float* b2     = (const float*)d_in[5];
    const float* W3     = (const float*)d_in[6];
    const float* b3     = (const float*)d_in[7];
    float* out = (float*)d_out;

    const int B = in_sizes[0] / 4;
    const int smem_bytes = SMEM_FLOATS * 4;  // 228,544 bytes
    cudaFuncSetAttribute(rqs_fused_kernel,
                         cudaFuncAttributeMaxDynamicSharedMemorySize, smem_bytes);
    rqs_fused_kernel<<<B / 128, 256, smem_bytes>>>(inputs, cond, W1, b1, W2, b2,
                                                   W3, b3, out, B);
}